// round 5
// baseline (speedup 1.0000x reference)
#include <cuda_runtime.h>
#include <math.h>

#define N_NODES   15000
#define N_EDGES   60000
#define EDGE_VOCAB 54
#define NODE_INDIM 64
#define EDGE_INDIM 32
#define H  32
#define EH 64
#define NBOND 4
#define NUM_STEPS 3
#define G   148                    // persistent blocks, 1 per SM
#define TPB 768
#define WPB (TPB / 32)
#define NWARPS (G * WPB)
#define CHUNK ((N_EDGES + G - 1) / G)

// ---------------- device scratch (no allocation allowed) -------------------
__device__ __align__(16) float g_Wv[EDGE_VOCAB * H * H];
__device__ __align__(16) float g_h[N_NODES * H];
__device__ __align__(16) float g_agg[N_NODES * H];
__device__ __align__(16) float g_Wpk[32 * 64 * 4];   // packed GRU weights (float4 pairs)
__device__ float g_p[N_NODES];
__device__ float g_q[N_NODES];
__device__ float g_nsum[N_NODES];
__device__ int   g_blockcnt[G * 64];
__device__ int   g_boff[G * 64];
__device__ int   g_e1[N_EDGES];       // src | (edge_id << 16), sorted by edge_id
__device__ int   g_e2[N_EDGES];       // dst, sorted by edge_id
__device__ int           g_bar_count = 0;
__device__ volatile int  g_bar_sense = 0;

// sense-reversing grid barrier; called an EVEN number of times per launch
__device__ __forceinline__ void grid_barrier(int* bsense) {
    __syncthreads();
    if (threadIdx.x == 0) {
        int my = *bsense ^ 1;
        __threadfence();
        if (atomicAdd(&g_bar_count, 1) == G - 1) {
            g_bar_count = 0;
            __threadfence();
            g_bar_sense = my;
        } else {
            while (g_bar_sense != my) { __nanosleep(32); }
        }
        __threadfence();
        *bsense = my;
    }
    __syncthreads();
}

__global__ void __launch_bounds__(TPB, 1)
k_fused(const int* __restrict__ node_ids, const int* __restrict__ edge_ids,
        const int* __restrict__ src, const int* __restrict__ dst,
        const float* __restrict__ node_table, const float* __restrict__ edge_table,
        const float* __restrict__ projW, const float* __restrict__ projb,
        const float* __restrict__ attn_w,
        const float* __restrict__ e1W1, const float* __restrict__ e1b1,
        const float* __restrict__ e1W2, const float* __restrict__ e1b2,
        const float* __restrict__ e2W1, const float* __restrict__ e2b1,
        const float* __restrict__ e2W2, const float* __restrict__ e2b2,
        const float* __restrict__ Wih, const float* __restrict__ Whh,
        const float* __restrict__ bih, const float* __restrict__ bhh,
        float* __restrict__ out) {
    __shared__ float S[NODE_INDIM * H];    // proj weights (transposed) / wvocab tmp
    __shared__ int   SI[64];
    __shared__ int   bsense;

    const int t    = threadIdx.x;
    const int b    = blockIdx.x;
    const int warp = t >> 5;
    const int lane = t & 31;
    const int gwarp = b * WPB + warp;

    if (t == 0) bsense = 0;
    __syncthreads();

    const int ebase = b * CHUNK;
    const int eend  = min(ebase + CHUNK, N_EDGES);

    // ================= phase 0: histogram + vocab W + GRU weight packing ===
    if (t < EDGE_VOCAB) SI[t] = 0;
    __syncthreads();
    for (int e = ebase + t; e < eend; e += TPB) atomicAdd(&SI[edge_ids[e]], 1);
    __syncthreads();
    if (t < EDGE_VOCAB) g_blockcnt[b * 64 + t] = SI[t];

    if (b < EDGE_VOCAB) {   // one block per vocab entry computes its W matrix
        const int v = b;
        const bool bond = (v < NBOND);
        const float* W1 = bond ? e1W1 : e2W1;
        const float* b1 = bond ? e1b1 : e2b1;
        const float* W2 = bond ? e1W2 : e2W2;
        const float* b2 = bond ? e1b2 : e2b2;
        float* ef = S;          // [32]
        float* z  = S + 32;     // [64]
        if (t < EDGE_INDIM) ef[t] = edge_table[v * EDGE_INDIM + t];
        __syncthreads();
        if (t < EH) {
            float acc = b1[t];
            #pragma unroll
            for (int i = 0; i < EDGE_INDIM; i++) acc += ef[i] * W1[t * EDGE_INDIM + i];
            z[t] = fmaxf(acc, 0.0f);
        }
        __syncthreads();
        for (int o = t; o < H * H; o += TPB) {
            float acc = b2[o];
            const float* w = W2 + o * EH;
            #pragma unroll
            for (int k = 0; k < EH; k++) acc += z[k] * w[k];
            g_Wv[v * H * H + o] = acc;
        }
    } else if (b == EDGE_VOCAB) {
        // pack GRU weights: g_Wpk[(k*64 + o*2 + m)*4 + g] where m=0 -> Wih, m=1 -> Whh
        for (int f = t; f < 32 * 64 * 4; f += TPB) {
            int comp = f & 3;          // gate (0..2), 3 = pad
            int f4   = f >> 2;
            int k    = f4 >> 6;
            int r    = f4 & 63;
            int o    = r >> 1;
            int m    = r & 1;
            float val = 0.0f;
            if (comp < 3) {
                const float* Wsrc = m ? Whh : Wih;
                val = Wsrc[(comp * 32 + o) * H + k];
            }
            g_Wpk[f] = val;
        }
    }
    grid_barrier(&bsense);                                     // B1

    // ================= phase 1: offsets scan (block 0 only) ================
    if (b == 0) {
        if (t < EDGE_VOCAB) {
            int tot = 0;
            for (int bb = 0; bb < G; bb++) tot += g_blockcnt[bb * 64 + t];
            SI[t] = tot;
        }
        __syncthreads();
        if (t == 0) {
            int acc = 0;
            for (int v = 0; v < EDGE_VOCAB; v++) { int c = SI[v]; SI[v] = acc; acc += c; }
        }
        __syncthreads();
        if (t < EDGE_VOCAB) {
            int run = SI[t];
            for (int bb = 0; bb < G; bb++) {
                g_boff[bb * 64 + t] = run;
                run += g_blockcnt[bb * 64 + t];
            }
        }
    }
    grid_barrier(&bsense);                                     // B2

    // ================= phase 2: scatter (sort by vocab) + init h ===========
    if (t < EDGE_VOCAB) SI[t] = g_boff[b * 64 + t];
    __syncthreads();
    for (int e = ebase + t; e < eend; e += TPB) {
        int id = edge_ids[e];
        int pos = atomicAdd(&SI[id], 1);
        g_e1[pos] = src[e] | (id << 16);
        g_e2[pos] = dst[e];
    }
    // init h = relu(nf @ projW^T + b), attention dots, accumulator reset
    {
        for (int idx = t; idx < H * NODE_INDIM; idx += TPB) {
            int o = idx / NODE_INDIM, i = idx % NODE_INDIM;
            S[i * H + o] = projW[idx];
        }
        __syncthreads();
        float aw0 = attn_w[lane], aw1 = attn_w[H + lane];
        for (int v = gwarp; v < N_NODES; v += NWARPS) {
            int nid = node_ids[v];
            const float* nf = node_table + nid * NODE_INDIM;
            float v0 = nf[lane];
            float v1 = nf[lane + 32];
            float acc = projb[lane];
            #pragma unroll
            for (int i = 0; i < 32; i++)
                acc += __shfl_sync(0xffffffffu, v0, i) * S[i * H + lane];
            #pragma unroll
            for (int i = 0; i < 32; i++)
                acc += __shfl_sync(0xffffffffu, v1, i) * S[(i + 32) * H + lane];
            float hv = fmaxf(acc, 0.0f);
            g_h[v * H + lane] = hv;
            g_agg[v * H + lane] = 0.0f;
            float pv = hv * aw0;
            float qv = hv * aw1;
            #pragma unroll
            for (int off = 16; off; off >>= 1) {
                pv += __shfl_down_sync(0xffffffffu, pv, off);
                qv += __shfl_down_sync(0xffffffffu, qv, off);
            }
            if (lane == 0) { g_p[v] = pv; g_q[v] = qv; g_nsum[v] = 0.0f; }
        }
    }
    grid_barrier(&bsense);                                     // B3

    // ================= message passing steps ===============================
    const float b_i0 = bih[lane], b_i1 = bih[32 + lane], b_i2 = bih[64 + lane];
    const float b_h0 = bhh[lane], b_h1 = bhh[32 + lane], b_h2 = bhh[64 + lane];
    const float aw0 = attn_w[lane], aw1 = attn_w[H + lane];

    for (int step = 0; step < NUM_STEPS; step++) {
        // ---- edge phase: lane-per-edge, W via broadcast-coalesced global ld
        {
            int len = eend - ebase;
            int ngroups = (len + 31) / 32;
            for (int grp = warp; grp < ngroups; grp += WPB) {
                int pos  = ebase + grp * 32 + lane;
                bool valid = (pos < eend);
                int cpos = valid ? pos : (eend - 1);
                int e1 = g_e1[cpos];
                int d  = g_e2[cpos];
                int s  = e1 & 0xFFFF;
                int id = e1 >> 16;
                float a = g_p[s] + g_q[d];
                a = (a > 0.0f) ? a : 0.01f * a;        // leaky_relu
                float ex = expf(a);                    // shift-free softmax
                // load h_src into registers (8 x LDG.128)
                float hr[32];
                {
                    const float4* hsrc = (const float4*)(g_h + s * H);
                    float4* hr4 = (float4*)hr;
                    #pragma unroll
                    for (int j = 0; j < 8; j++) hr4[j] = hsrc[j];
                }
                const float4* Wb = (const float4*)g_Wv + id * (H * H / 4);
                float* aggrow = g_agg + d * H;
                // half 0: outputs 0..15
                {
                    float4 A0 = {0,0,0,0}, A1 = {0,0,0,0}, A2 = {0,0,0,0}, A3 = {0,0,0,0};
                    #pragma unroll
                    for (int k = 0; k < 32; k++) {
                        float hk = hr[k];
                        float4 w0 = Wb[k * 8 + 0], w1 = Wb[k * 8 + 1];
                        float4 w2 = Wb[k * 8 + 2], w3 = Wb[k * 8 + 3];
                        A0.x += hk * w0.x; A0.y += hk * w0.y; A0.z += hk * w0.z; A0.w += hk * w0.w;
                        A1.x += hk * w1.x; A1.y += hk * w1.y; A1.z += hk * w1.z; A1.w += hk * w1.w;
                        A2.x += hk * w2.x; A2.y += hk * w2.y; A2.z += hk * w2.z; A2.w += hk * w2.w;
                        A3.x += hk * w3.x; A3.y += hk * w3.y; A3.z += hk * w3.z; A3.w += hk * w3.w;
                    }
                    if (valid) {
                        asm volatile("red.global.add.v4.f32 [%0], {%1,%2,%3,%4};" ::
                            "l"(aggrow + 0), "f"(A0.x*ex), "f"(A0.y*ex), "f"(A0.z*ex), "f"(A0.w*ex) : "memory");
                        asm volatile("red.global.add.v4.f32 [%0], {%1,%2,%3,%4};" ::
                            "l"(aggrow + 4), "f"(A1.x*ex), "f"(A1.y*ex), "f"(A1.z*ex), "f"(A1.w*ex) : "memory");
                        asm volatile("red.global.add.v4.f32 [%0], {%1,%2,%3,%4};" ::
                            "l"(aggrow + 8), "f"(A2.x*ex), "f"(A2.y*ex), "f"(A2.z*ex), "f"(A2.w*ex) : "memory");
                        asm volatile("red.global.add.v4.f32 [%0], {%1,%2,%3,%4};" ::
                            "l"(aggrow + 12), "f"(A3.x*ex), "f"(A3.y*ex), "f"(A3.z*ex), "f"(A3.w*ex) : "memory");
                    }
                }
                // half 1: outputs 16..31
                {
                    float4 A0 = {0,0,0,0}, A1 = {0,0,0,0}, A2 = {0,0,0,0}, A3 = {0,0,0,0};
                    #pragma unroll
                    for (int k = 0; k < 32; k++) {
                        float hk = hr[k];
                        float4 w0 = Wb[k * 8 + 4], w1 = Wb[k * 8 + 5];
                        float4 w2 = Wb[k * 8 + 6], w3 = Wb[k * 8 + 7];
                        A0.x += hk * w0.x; A0.y += hk * w0.y; A0.z += hk * w0.z; A0.w += hk * w0.w;
                        A1.x += hk * w1.x; A1.y += hk * w1.y; A1.z += hk * w1.z; A1.w += hk * w1.w;
                        A2.x += hk * w2.x; A2.y += hk * w2.y; A2.z += hk * w2.z; A2.w += hk * w2.w;
                        A3.x += hk * w3.x; A3.y += hk * w3.y; A3.z += hk * w3.z; A3.w += hk * w3.w;
                    }
                    if (valid) {
                        asm volatile("red.global.add.v4.f32 [%0], {%1,%2,%3,%4};" ::
                            "l"(aggrow + 16), "f"(A0.x*ex), "f"(A0.y*ex), "f"(A0.z*ex), "f"(A0.w*ex) : "memory");
                        asm volatile("red.global.add.v4.f32 [%0], {%1,%2,%3,%4};" ::
                            "l"(aggrow + 20), "f"(A1.x*ex), "f"(A1.y*ex), "f"(A1.z*ex), "f"(A1.w*ex) : "memory");
                        asm volatile("red.global.add.v4.f32 [%0], {%1,%2,%3,%4};" ::
                            "l"(aggrow + 24), "f"(A2.x*ex), "f"(A2.y*ex), "f"(A2.z*ex), "f"(A2.w*ex) : "memory");
                        asm volatile("red.global.add.v4.f32 [%0], {%1,%2,%3,%4};" ::
                            "l"(aggrow + 28), "f"(A3.x*ex), "f"(A3.y*ex), "f"(A3.z*ex), "f"(A3.w*ex) : "memory");
                        atomicAdd(&g_nsum[d], ex);
                    }
                }
            }
        }
        grid_barrier(&bsense);                                 // B-edge (x3)

        // ---- GRU phase: packed float4 weights from global (L1-resident)
        {
            const int last = (step == NUM_STEPS - 1);
            const float4* Wpk = (const float4*)g_Wpk;
            for (int v = gwarp; v < N_NODES; v += NWARPS) {
                float ns = g_nsum[v];
                float inv = (ns > 0.0f) ? (1.0f / ns) : 0.0f;
                float m  = fmaxf(g_agg[v * H + lane] * inv, 0.0f);
                float hv = g_h[v * H + lane];
                float gi0 = b_i0, gi1 = b_i1, gi2 = b_i2;
                float gh0 = b_h0, gh1 = b_h1, gh2 = b_h2;
                #pragma unroll
                for (int k = 0; k < H; k++) {
                    float mi = __shfl_sync(0xffffffffu, m, k);
                    float hi = __shfl_sync(0xffffffffu, hv, k);
                    float4 wi = Wpk[k * 64 + lane * 2];
                    float4 wh = Wpk[k * 64 + lane * 2 + 1];
                    gi0 += mi * wi.x; gi1 += mi * wi.y; gi2 += mi * wi.z;
                    gh0 += hi * wh.x; gh1 += hi * wh.y; gh2 += hi * wh.z;
                }
                float r = 1.0f / (1.0f + expf(-(gi0 + gh0)));
                float z = 1.0f / (1.0f + expf(-(gi1 + gh1)));
                float n = tanhf(gi2 + r * gh2);
                float hnew = (1.0f - z) * n + z * hv;
                g_h[v * H + lane] = hnew;
                if (last) {
                    out[v * H + lane] = hnew;
                } else {
                    g_agg[v * H + lane] = 0.0f;
                    float pv = hnew * aw0;
                    float qv = hnew * aw1;
                    #pragma unroll
                    for (int off = 16; off; off >>= 1) {
                        pv += __shfl_down_sync(0xffffffffu, pv, off);
                        qv += __shfl_down_sync(0xffffffffu, qv, off);
                    }
                    if (lane == 0) { g_p[v] = pv; g_q[v] = qv; g_nsum[v] = 0.0f; }
                }
            }
        }
        if (step < NUM_STEPS - 1) grid_barrier(&bsense);       // B-gru (x2)
    }
    // barriers per call: 3 + 3 + 2 = 8 (even) -> sense returns to 0 for replay
}

// ---------------- launch ----------------------------------------------------
extern "C" void kernel_launch(void* const* d_in, const int* in_sizes, int n_in,
                              void* d_out, int out_size) {
    k_fused<<<G, TPB>>>(
        (const int*)d_in[0], (const int*)d_in[1], (const int*)d_in[2],
        (const int*)d_in[3], (const float*)d_in[4], (const float*)d_in[5],
        (const float*)d_in[6], (const float*)d_in[7], (const float*)d_in[8],
        (const float*)d_in[9], (const float*)d_in[10], (const float*)d_in[11],
        (const float*)d_in[12], (const float*)d_in[13], (const float*)d_in[14],
        (const float*)d_in[15], (const float*)d_in[16], (const float*)d_in[17],
        (const float*)d_in[18], (const float*)d_in[19], (const float*)d_in[20],
        (float*)d_out);
}

// round 7
// speedup vs baseline: 1.2700x; 1.2700x over previous
#include <cuda_runtime.h>
#include <math.h>

#define N_NODES   15000
#define N_EDGES   60000
#define EDGE_VOCAB 54
#define NODE_INDIM 64
#define EDGE_INDIM 32
#define H  32
#define EH 64
#define NBOND 4
#define NUM_STEPS 3
#define G   148                    // persistent blocks, 1 per SM
#define TPB 768
#define WPB (TPB / 32)
#define NWARPS (G * WPB)
#define CHUNK ((N_EDGES + G - 1) / G)

// ---------------- device scratch (no allocation allowed) -------------------
__device__ __align__(16) float  g_Wv[EDGE_VOCAB * H * H];
__device__ __align__(16) float  g_h[N_NODES * H];
__device__ __align__(16) float  g_agg[N_NODES * H];
__device__ __align__(16) float4 g_Wpk4[2 * 32 * 32];   // packed GRU weights
__device__ float g_p[N_NODES];
__device__ float g_q[N_NODES];
__device__ float g_nsum[N_NODES];
__device__ int   g_blockcnt[G * 64];
__device__ int   g_boff[G * 64];
__device__ int   g_e1[N_EDGES];       // src | (edge_id << 16), sorted by edge_id
__device__ int   g_e2[N_EDGES];       // dst, sorted by edge_id
__device__ int           g_bar_count = 0;
__device__ volatile int  g_bar_sense = 0;

// sense-reversing grid barrier; called an EVEN number of times per launch
__device__ __forceinline__ void grid_barrier(int* bsense) {
    __syncthreads();
    if (threadIdx.x == 0) {
        int my = *bsense ^ 1;
        __threadfence();
        if (atomicAdd(&g_bar_count, 1) == G - 1) {
            g_bar_count = 0;
            __threadfence();
            g_bar_sense = my;
        } else {
            while (g_bar_sense != my) { __nanosleep(32); }
        }
        __threadfence();
        *bsense = my;
    }
    __syncthreads();
}

__device__ __forceinline__ float sigmoidf_fast(float x) {
    return __fdividef(1.0f, 1.0f + __expf(-x));
}

__global__ void __launch_bounds__(TPB, 1)
k_fused(const int* __restrict__ node_ids, const int* __restrict__ edge_ids,
        const int* __restrict__ src, const int* __restrict__ dst,
        const float* __restrict__ node_table, const float* __restrict__ edge_table,
        const float* __restrict__ projW, const float* __restrict__ projb,
        const float* __restrict__ attn_w,
        const float* __restrict__ e1W1, const float* __restrict__ e1b1,
        const float* __restrict__ e1W2, const float* __restrict__ e1b2,
        const float* __restrict__ e2W1, const float* __restrict__ e2b1,
        const float* __restrict__ e2W2, const float* __restrict__ e2b2,
        const float* __restrict__ Wih, const float* __restrict__ Whh,
        const float* __restrict__ bih, const float* __restrict__ bhh,
        float* __restrict__ out) {
    __shared__ float S[NODE_INDIM * H];    // proj weights / wvocab tmp (8 KB)
    __shared__ int   SI[64];
    __shared__ int   bsense;

    const int t    = threadIdx.x;
    const int b    = blockIdx.x;
    const int warp = t >> 5;
    const int lane = t & 31;
    const int gwarp = b * WPB + warp;

    if (t == 0) bsense = 0;
    __syncthreads();

    const int ebase = b * CHUNK;
    const int eend  = min(ebase + CHUNK, N_EDGES);

    // ================= phase 0: histogram + vocab W + GRU weight packing ===
    if (t < EDGE_VOCAB) SI[t] = 0;
    __syncthreads();
    for (int e = ebase + t; e < eend; e += TPB) atomicAdd(&SI[edge_ids[e]], 1);
    __syncthreads();
    if (t < EDGE_VOCAB) g_blockcnt[b * 64 + t] = SI[t];

    if (b < EDGE_VOCAB) {   // one block per vocab entry computes its W matrix
        const int v = b;
        const bool bond = (v < NBOND);
        const float* W1 = bond ? e1W1 : e2W1;
        const float* b1 = bond ? e1b1 : e2b1;
        const float* W2 = bond ? e1W2 : e2W2;
        const float* b2 = bond ? e1b2 : e2b2;
        float* ef = S;          // [32]
        float* z  = S + 32;     // [64]
        if (t < EDGE_INDIM) ef[t] = edge_table[v * EDGE_INDIM + t];
        __syncthreads();
        if (t < EH) {
            float acc = b1[t];
            #pragma unroll
            for (int i = 0; i < EDGE_INDIM; i++) acc += ef[i] * W1[t * EDGE_INDIM + i];
            z[t] = fmaxf(acc, 0.0f);
        }
        __syncthreads();
        for (int o = t; o < H * H; o += TPB) {
            float acc = b2[o];
            const float* w = W2 + o * EH;
            #pragma unroll
            for (int k = 0; k < EH; k++) acc += z[k] * w[k];
            g_Wv[v * H * H + o] = acc;
        }
    } else if (b == EDGE_VOCAB) {
        // pack GRU weights: g_Wpk4[m*1024 + k*32 + o] = {W[0*32+o][k], W[32+o][k], W[64+o][k], 0}
        for (int f = t; f < 2048; f += TPB) {
            int mm = f >> 10, r = f & 1023, k = r >> 5, o = r & 31;
            const float* Wsrc = mm ? Whh : Wih;
            g_Wpk4[f] = make_float4(Wsrc[o * H + k],
                                    Wsrc[(32 + o) * H + k],
                                    Wsrc[(64 + o) * H + k], 0.0f);
        }
    }
    grid_barrier(&bsense);                                     // B1

    // ================= phase 1: offsets scan (block 0 only) ================
    if (b == 0) {
        if (t < EDGE_VOCAB) {
            int tot = 0;
            for (int bb = 0; bb < G; bb++) tot += g_blockcnt[bb * 64 + t];
            SI[t] = tot;
        }
        __syncthreads();
        if (t == 0) {
            int acc = 0;
            for (int v = 0; v < EDGE_VOCAB; v++) { int c = SI[v]; SI[v] = acc; acc += c; }
        }
        __syncthreads();
        if (t < EDGE_VOCAB) {
            int run = SI[t];
            for (int bb = 0; bb < G; bb++) {
                g_boff[bb * 64 + t] = run;
                run += g_blockcnt[bb * 64 + t];
            }
        }
    }
    grid_barrier(&bsense);                                     // B2

    // ================= phase 2: scatter (sort by vocab) + init h ===========
    if (t < EDGE_VOCAB) SI[t] = g_boff[b * 64 + t];
    __syncthreads();
    for (int e = ebase + t; e < eend; e += TPB) {
        int id = edge_ids[e];
        int pos = atomicAdd(&SI[id], 1);
        g_e1[pos] = src[e] | (id << 16);
        g_e2[pos] = dst[e];
    }
    // init h = relu(nf @ projW^T + b), attention dots, accumulator reset
    {
        for (int idx = t; idx < H * NODE_INDIM; idx += TPB) {
            int o = idx / NODE_INDIM, i = idx % NODE_INDIM;
            S[i * H + o] = projW[idx];
        }
        __syncthreads();
        float aw0 = attn_w[lane], aw1 = attn_w[H + lane];
        for (int v = gwarp; v < N_NODES; v += NWARPS) {
            int nid = node_ids[v];
            const float* nf = node_table + nid * NODE_INDIM;
            float v0 = nf[lane];
            float v1 = nf[lane + 32];
            float acc = projb[lane];
            #pragma unroll
            for (int i = 0; i < 32; i++)
                acc += __shfl_sync(0xffffffffu, v0, i) * S[i * H + lane];
            #pragma unroll
            for (int i = 0; i < 32; i++)
                acc += __shfl_sync(0xffffffffu, v1, i) * S[(i + 32) * H + lane];
            float hv = fmaxf(acc, 0.0f);
            g_h[v * H + lane] = hv;
            g_agg[v * H + lane] = 0.0f;
            float pv = hv * aw0;
            float qv = hv * aw1;
            #pragma unroll
            for (int off = 16; off; off >>= 1) {
                pv += __shfl_down_sync(0xffffffffu, pv, off);
                qv += __shfl_down_sync(0xffffffffu, qv, off);
            }
            if (lane == 0) { g_p[v] = pv; g_q[v] = qv; g_nsum[v] = 0.0f; }
        }
    }
    grid_barrier(&bsense);                                     // B3

    // ================= message passing steps ===============================
    const float b_i0 = bih[lane], b_i1 = bih[32 + lane], b_i2 = bih[64 + lane];
    const float b_h0 = bhh[lane], b_h1 = bhh[32 + lane], b_h2 = bhh[64 + lane];
    const float aw0 = attn_w[lane], aw1 = attn_w[H + lane];

    for (int step = 0; step < NUM_STEPS; step++) {
        // ---- edge phase: warp-per-edge, W in registers, broadcast h loads
        {
            int len = eend - ebase;
            int per = (len + WPB - 1) / WPB;
            int w0 = ebase + warp * per;
            int w1 = min(w0 + per, eend);
            int cached = -1;
            float Wr[32];
            for (int pos = w0; pos < w1; pos++) {
                int e1 = g_e1[pos];
                int d  = g_e2[pos];
                int s  = e1 & 0xFFFF;
                int id = e1 >> 16;
                if (id != cached) {
                    cached = id;
                    const float* Wp = g_Wv + id * (H * H) + lane;
                    #pragma unroll
                    for (int k = 0; k < 32; k++) Wr[k] = Wp[k * 32];
                }
                float a = g_p[s] + g_q[d];
                a = (a > 0.0f) ? a : 0.01f * a;        // leaky_relu
                float ex = __expf(a);                  // shift-free softmax
                const float4* h4 = (const float4*)(g_h + s * H);
                float a0 = 0.0f, a1 = 0.0f, a2 = 0.0f, a3 = 0.0f;
                float hr[16];
                // first half: k = 0..15
                ((float4*)hr)[0] = h4[0];
                ((float4*)hr)[1] = h4[1];
                ((float4*)hr)[2] = h4[2];
                ((float4*)hr)[3] = h4[3];
                #pragma unroll
                for (int k = 0; k < 16; k += 4) {
                    a0 = fmaf(hr[k + 0], Wr[k + 0], a0);
                    a1 = fmaf(hr[k + 1], Wr[k + 1], a1);
                    a2 = fmaf(hr[k + 2], Wr[k + 2], a2);
                    a3 = fmaf(hr[k + 3], Wr[k + 3], a3);
                }
                // second half: k = 16..31
                ((float4*)hr)[0] = h4[4];
                ((float4*)hr)[1] = h4[5];
                ((float4*)hr)[2] = h4[6];
                ((float4*)hr)[3] = h4[7];
                #pragma unroll
                for (int k = 0; k < 16; k += 4) {
                    a0 = fmaf(hr[k + 0], Wr[16 + k + 0], a0);
                    a1 = fmaf(hr[k + 1], Wr[16 + k + 1], a1);
                    a2 = fmaf(hr[k + 2], Wr[16 + k + 2], a2);
                    a3 = fmaf(hr[k + 3], Wr[16 + k + 3], a3);
                }
                float acc = ((a0 + a1) + (a2 + a3)) * ex;
                atomicAdd(&g_agg[d * H + lane], acc);
                if (lane == 0) atomicAdd(&g_nsum[d], ex);
            }
        }
        grid_barrier(&bsense);                                 // B-edge (x3)

        // ---- GRU phase: 4 nodes per warp, packed float4 weights (L1)
        {
            const int last = (step == NUM_STEPS - 1);
            const float4* __restrict__ Wpk = g_Wpk4;
            for (int v0 = gwarp * 4; v0 < N_NODES; v0 += NWARPS * 4) {
                float m[4], hv[4];
                float gi[4][3], gh[4][3];
                #pragma unroll
                for (int j = 0; j < 4; j++) {
                    int v = min(v0 + j, N_NODES - 1);
                    float ns = g_nsum[v];
                    float inv = (ns > 0.0f) ? __fdividef(1.0f, ns) : 0.0f;
                    m[j]  = fmaxf(g_agg[v * H + lane] * inv, 0.0f);
                    hv[j] = g_h[v * H + lane];
                    gi[j][0] = b_i0; gi[j][1] = b_i1; gi[j][2] = b_i2;
                    gh[j][0] = b_h0; gh[j][1] = b_h1; gh[j][2] = b_h2;
                }
                #pragma unroll
                for (int k = 0; k < 32; k++) {
                    float4 wi = Wpk[k * 32 + lane];
                    float4 wh = Wpk[1024 + k * 32 + lane];
                    #pragma unroll
                    for (int j = 0; j < 4; j++) {
                        float mi = __shfl_sync(0xffffffffu, m[j], k);
                        float hi = __shfl_sync(0xffffffffu, hv[j], k);
                        gi[j][0] = fmaf(mi, wi.x, gi[j][0]);
                        gi[j][1] = fmaf(mi, wi.y, gi[j][1]);
                        gi[j][2] = fmaf(mi, wi.z, gi[j][2]);
                        gh[j][0] = fmaf(hi, wh.x, gh[j][0]);
                        gh[j][1] = fmaf(hi, wh.y, gh[j][1]);
                        gh[j][2] = fmaf(hi, wh.z, gh[j][2]);
                    }
                }
                #pragma unroll
                for (int j = 0; j < 4; j++) {
                    int v = v0 + j;
                    if (v >= N_NODES) break;
                    float r = sigmoidf_fast(gi[j][0] + gh[j][0]);
                    float z = sigmoidf_fast(gi[j][1] + gh[j][1]);
                    float n = tanhf(gi[j][2] + r * gh[j][2]);
                    float hnew = (1.0f - z) * n + z * hv[j];
                    g_h[v * H + lane] = hnew;
                    if (last) {
                        out[v * H + lane] = hnew;
                    } else {
                        g_agg[v * H + lane] = 0.0f;
                        float pv = hnew * aw0;
                        float qv = hnew * aw1;
                        #pragma unroll
                        for (int off = 16; off; off >>= 1) {
                            pv += __shfl_down_sync(0xffffffffu, pv, off);
                            qv += __shfl_down_sync(0xffffffffu, qv, off);
                        }
                        if (lane == 0) { g_p[v] = pv; g_q[v] = qv; g_nsum[v] = 0.0f; }
                    }
                }
            }
        }
        if (step < NUM_STEPS - 1) grid_barrier(&bsense);       // B-gru (x2)
    }
    // barriers per call: 3 + 3 + 2 = 8 (even) -> sense returns to 0 for replay
}

// ---------------- launch ----------------------------------------------------
extern "C" void kernel_launch(void* const* d_in, const int* in_sizes, int n_in,
                              void* d_out, int out_size) {
    k_fused<<<G, TPB>>>(
        (const int*)d_in[0], (const int*)d_in[1], (const int*)d_in[2],
        (const int*)d_in[3], (const float*)d_in[4], (const float*)d_in[5],
        (const float*)d_in[6], (const float*)d_in[7], (const float*)d_in[8],
        (const float*)d_in[9], (const float*)d_in[10], (const float*)d_in[11],
        (const float*)d_in[12], (const float*)d_in[13], (const float*)d_in[14],
        (const float*)d_in[15], (const float*)d_in[16], (const float*)d_in[17],
        (const float*)d_in[18], (const float*)d_in[19], (const float*)d_in[20],
        (float*)d_out);
}

// round 12
// speedup vs baseline: 1.3143x; 1.0349x over previous
#include <cuda_runtime.h>
#include <math.h>

#define N_NODES   15000
#define N_EDGES   60000
#define EDGE_VOCAB 54
#define NODE_INDIM 64
#define EDGE_INDIM 32
#define H  32
#define EH 64
#define NBOND 4
#define NUM_STEPS 3
#define G   148                    // persistent blocks, 1 per SM
#define TPB 768
#define WPB (TPB / 32)
#define NWARPS (G * WPB)
#define CHUNK ((N_EDGES + G - 1) / G)

// ---------------- device scratch (no allocation allowed) -------------------
__device__ __align__(16) float  g_Wv[EDGE_VOCAB * H * H];
__device__ __align__(16) float  g_h[N_NODES * H];
__device__ __align__(16) float  g_agg[N_NODES * H];
__device__ __align__(16) float4 g_Wpk4[2 * 32 * 32];   // packed GRU weights
__device__ float g_p[N_NODES];
__device__ float g_q[N_NODES];
__device__ float g_nsum[N_NODES];
__device__ int   g_blockcnt[G * 64];
__device__ __align__(8) int2 g_ed[N_EDGES];   // {src | id<<16, dst}, sorted by id
__device__ int           g_bar_count = 0;
__device__ volatile int  g_bar_sense = 0;

// sense-reversing grid barrier; sense is read at kernel entry, so any number
// of barriers per launch is replay-safe.
__device__ __forceinline__ void grid_barrier(int* bsense) {
    __syncthreads();
    if (threadIdx.x == 0) {
        int my = *bsense ^ 1;
        __threadfence();
        if (atomicAdd(&g_bar_count, 1) == G - 1) {
            g_bar_count = 0;
            __threadfence();
            g_bar_sense = my;
        } else {
            while (g_bar_sense != my) { __nanosleep(32); }
        }
        __threadfence();
        *bsense = my;
    }
    __syncthreads();
}

__device__ __forceinline__ float sigmoidf_fast(float x) {
    return __fdividef(1.0f, 1.0f + __expf(-x));
}

__global__ void __launch_bounds__(TPB, 1)
k_fused(const int* __restrict__ node_ids, const int* __restrict__ edge_ids,
        const int* __restrict__ src, const int* __restrict__ dst,
        const float* __restrict__ node_table, const float* __restrict__ edge_table,
        const float* __restrict__ projW, const float* __restrict__ projb,
        const float* __restrict__ attn_w,
        const float* __restrict__ e1W1, const float* __restrict__ e1b1,
        const float* __restrict__ e1W2, const float* __restrict__ e1b2,
        const float* __restrict__ e2W1, const float* __restrict__ e2b1,
        const float* __restrict__ e2W2, const float* __restrict__ e2b2,
        const float* __restrict__ Wih, const float* __restrict__ Whh,
        const float* __restrict__ bih, const float* __restrict__ bhh,
        float* __restrict__ out) {
    __shared__ float S[NODE_INDIM * H];    // proj weights / wvocab tmp (8 KB)
    __shared__ int   SI[64];
    __shared__ int   bsense_sh;

    const int t    = threadIdx.x;
    const int b    = blockIdx.x;
    const int warp = t >> 5;
    const int lane = t & 31;
    const int gwarp = b * WPB + warp;

    if (t == 0) bsense_sh = g_bar_sense;   // adaptive sense: any parity OK
    __syncthreads();
    int bsense = bsense_sh;

    const int ebase = b * CHUNK;
    const int eend  = min(ebase + CHUNK, N_EDGES);

    // ================= phase 0: histogram + vocab W + GRU weight packing ===
    if (t < EDGE_VOCAB) SI[t] = 0;
    __syncthreads();
    for (int e = ebase + t; e < eend; e += TPB) atomicAdd(&SI[edge_ids[e]], 1);
    __syncthreads();
    if (t < EDGE_VOCAB) g_blockcnt[b * 64 + t] = SI[t];

    if (b < EDGE_VOCAB) {   // one block per vocab entry computes its W matrix
        const int v = b;
        const bool bond = (v < NBOND);
        const float* W1 = bond ? e1W1 : e2W1;
        const float* b1 = bond ? e1b1 : e2b1;
        const float* W2 = bond ? e1W2 : e2W2;
        const float* b2 = bond ? e1b2 : e2b2;
        float* ef = S;          // [32]
        float* z  = S + 32;     // [64]
        if (t < EDGE_INDIM) ef[t] = edge_table[v * EDGE_INDIM + t];
        __syncthreads();
        if (t < EH) {
            float acc = b1[t];
            #pragma unroll
            for (int i = 0; i < EDGE_INDIM; i++) acc += ef[i] * W1[t * EDGE_INDIM + i];
            z[t] = fmaxf(acc, 0.0f);
        }
        __syncthreads();
        for (int o = t; o < H * H; o += TPB) {
            float acc = b2[o];
            const float* w = W2 + o * EH;
            #pragma unroll
            for (int k = 0; k < EH; k++) acc += z[k] * w[k];
            g_Wv[v * H * H + o] = acc;
        }
    } else if (b == EDGE_VOCAB) {
        // pack GRU weights: g_Wpk4[m*1024 + k*32 + o] = {W[o][k], W[32+o][k], W[64+o][k], 0}
        for (int f = t; f < 2048; f += TPB) {
            int mm = f >> 10, r = f & 1023, k = r >> 5, o = r & 31;
            const float* Wsrc = mm ? Whh : Wih;
            g_Wpk4[f] = make_float4(Wsrc[o * H + k],
                                    Wsrc[(32 + o) * H + k],
                                    Wsrc[(64 + o) * H + k], 0.0f);
        }
    }
    grid_barrier(&bsense);                                     // B1

    // ====== redundant per-block scan: every block computes its own offsets =
    // cursor[v] for this block = (global prefix of buckets < v)
    //                            + sum_{bb < b} cnt[bb][v]
    if (t < EDGE_VOCAB) {
        int tot = 0;
        for (int bb = 0; bb < G; bb++) tot += g_blockcnt[bb * 64 + t];
        SI[t] = tot;          // total size of bucket t
    }
    __syncthreads();
    if (t == 0) {
        int acc = 0;
        for (int v = 0; v < EDGE_VOCAB; v++) { int c = SI[v]; SI[v] = acc; acc += c; }
    }
    __syncthreads();
    if (t < EDGE_VOCAB) {
        int pre = 0;
        for (int bb = 0; bb < b; bb++) pre += g_blockcnt[bb * 64 + t];
        SI[t] = SI[t] + pre;   // this block's scatter cursor for bucket t
    }
    __syncthreads();

    // ================= phase 2: scatter (sort by vocab) + init h ===========
    for (int e = ebase + t; e < eend; e += TPB) {
        int id = edge_ids[e];
        int pos = atomicAdd(&SI[id], 1);
        g_ed[pos] = make_int2(src[e] | (id << 16), dst[e]);
    }
    // init h = relu(nf @ projW^T + b), attention dots, accumulator reset
    {
        for (int idx = t; idx < H * NODE_INDIM; idx += TPB) {
            int o = idx / NODE_INDIM, i = idx % NODE_INDIM;
            S[i * H + o] = projW[idx];
        }
        __syncthreads();
        float aw0 = attn_w[lane], aw1 = attn_w[H + lane];
        for (int v = gwarp; v < N_NODES; v += NWARPS) {
            int nid = node_ids[v];
            const float* nf = node_table + nid * NODE_INDIM;
            float v0 = nf[lane];
            float v1 = nf[lane + 32];
            float acc = projb[lane];
            #pragma unroll
            for (int i = 0; i < 32; i++)
                acc += __shfl_sync(0xffffffffu, v0, i) * S[i * H + lane];
            #pragma unroll
            for (int i = 0; i < 32; i++)
                acc += __shfl_sync(0xffffffffu, v1, i) * S[(i + 32) * H + lane];
            float hv = fmaxf(acc, 0.0f);
            g_h[v * H + lane] = hv;
            g_agg[v * H + lane] = 0.0f;
            float pv = hv * aw0;
            float qv = hv * aw1;
            #pragma unroll
            for (int off = 16; off; off >>= 1) {
                pv += __shfl_down_sync(0xffffffffu, pv, off);
                qv += __shfl_down_sync(0xffffffffu, qv, off);
            }
            if (lane == 0) { g_p[v] = pv; g_q[v] = qv; g_nsum[v] = 0.0f; }
        }
    }
    grid_barrier(&bsense);                                     // B2

    // ================= message passing steps ===============================
    const float b_i0 = bih[lane], b_i1 = bih[32 + lane], b_i2 = bih[64 + lane];
    const float b_h0 = bhh[lane], b_h1 = bhh[32 + lane], b_h2 = bhh[64 + lane];
    const float aw0 = attn_w[lane], aw1 = attn_w[H + lane];

    for (int step = 0; step < NUM_STEPS; step++) {
        // ---- edge phase: warp-per-edge, W in registers, prefetched loads
        {
            int len = eend - ebase;
            int per = (len + WPB - 1) / WPB;
            int w0 = ebase + warp * per;
            int w1 = min(w0 + per, eend);
            int cached = -1;
            float Wr[32];
            if (w0 < w1) {
                // prefetch pipeline: ed/p/q one edge ahead
                int2 ed = g_ed[w0];
                float pn = g_p[ed.x & 0xFFFF];
                float qn = g_q[ed.y];
                for (int pos = w0; pos < w1; pos++) {
                    int2 cur = ed;
                    float pc = pn, qc = qn;
                    if (pos + 1 < w1) {
                        ed = g_ed[pos + 1];
                        pn = g_p[ed.x & 0xFFFF];
                        qn = g_q[ed.y];
                    }
                    int s  = cur.x & 0xFFFF;
                    int id = cur.x >> 16;
                    int d  = cur.y;
                    if (id != cached) {
                        cached = id;
                        const float* Wp = g_Wv + id * (H * H) + lane;
                        #pragma unroll
                        for (int k = 0; k < 32; k++) Wr[k] = Wp[k * 32];
                    }
                    float a = pc + qc;
                    a = (a > 0.0f) ? a : 0.01f * a;        // leaky_relu
                    float ex = __expf(a);                  // shift-free softmax
                    const float4* h4 = (const float4*)(g_h + s * H);
                    float a0 = 0.0f, a1 = 0.0f, a2 = 0.0f, a3 = 0.0f;
                    float hr[16];
                    ((float4*)hr)[0] = h4[0];
                    ((float4*)hr)[1] = h4[1];
                    ((float4*)hr)[2] = h4[2];
                    ((float4*)hr)[3] = h4[3];
                    #pragma unroll
                    for (int k = 0; k < 16; k += 4) {
                        a0 = fmaf(hr[k + 0], Wr[k + 0], a0);
                        a1 = fmaf(hr[k + 1], Wr[k + 1], a1);
                        a2 = fmaf(hr[k + 2], Wr[k + 2], a2);
                        a3 = fmaf(hr[k + 3], Wr[k + 3], a3);
                    }
                    ((float4*)hr)[0] = h4[4];
                    ((float4*)hr)[1] = h4[5];
                    ((float4*)hr)[2] = h4[6];
                    ((float4*)hr)[3] = h4[7];
                    #pragma unroll
                    for (int k = 0; k < 16; k += 4) {
                        a0 = fmaf(hr[k + 0], Wr[16 + k + 0], a0);
                        a1 = fmaf(hr[k + 1], Wr[16 + k + 1], a1);
                        a2 = fmaf(hr[k + 2], Wr[16 + k + 2], a2);
                        a3 = fmaf(hr[k + 3], Wr[16 + k + 3], a3);
                    }
                    float acc = ((a0 + a1) + (a2 + a3)) * ex;
                    atomicAdd(&g_agg[d * H + lane], acc);
                    if (lane == 0) atomicAdd(&g_nsum[d], ex);
                }
            }
        }
        grid_barrier(&bsense);                                 // B-edge (x3)

        // ---- GRU phase: 4 nodes per warp, packed float4 weights (L1)
        {
            const int last = (step == NUM_STEPS - 1);
            const float4* __restrict__ Wpk = g_Wpk4;
            for (int v0 = gwarp * 4; v0 < N_NODES; v0 += NWARPS * 4) {
                float m[4], hv[4];
                float gi[4][3], gh[4][3];
                #pragma unroll
                for (int j = 0; j < 4; j++) {
                    int v = min(v0 + j, N_NODES - 1);
                    float ns = g_nsum[v];
                    float inv = (ns > 0.0f) ? __fdividef(1.0f, ns) : 0.0f;
                    m[j]  = fmaxf(g_agg[v * H + lane] * inv, 0.0f);
                    hv[j] = g_h[v * H + lane];
                    gi[j][0] = b_i0; gi[j][1] = b_i1; gi[j][2] = b_i2;
                    gh[j][0] = b_h0; gh[j][1] = b_h1; gh[j][2] = b_h2;
                }
                #pragma unroll
                for (int k = 0; k < 32; k++) {
                    float4 wi = Wpk[k * 32 + lane];
                    float4 wh = Wpk[1024 + k * 32 + lane];
                    #pragma unroll
                    for (int j = 0; j < 4; j++) {
                        float mi = __shfl_sync(0xffffffffu, m[j], k);
                        float hi = __shfl_sync(0xffffffffu, hv[j], k);
                        gi[j][0] = fmaf(mi, wi.x, gi[j][0]);
                        gi[j][1] = fmaf(mi, wi.y, gi[j][1]);
                        gi[j][2] = fmaf(mi, wi.z, gi[j][2]);
                        gh[j][0] = fmaf(hi, wh.x, gh[j][0]);
                        gh[j][1] = fmaf(hi, wh.y, gh[j][1]);
                        gh[j][2] = fmaf(hi, wh.z, gh[j][2]);
                    }
                }
                #pragma unroll
                for (int j = 0; j < 4; j++) {
                    int v = v0 + j;
                    if (v >= N_NODES) break;
                    float r = sigmoidf_fast(gi[j][0] + gh[j][0]);
                    float z = sigmoidf_fast(gi[j][1] + gh[j][1]);
                    float n = tanhf(gi[j][2] + r * gh[j][2]);
                    float hnew = (1.0f - z) * n + z * hv[j];
                    if (last) {
                        out[v * H + lane] = hnew;
                    } else {
                        g_h[v * H + lane] = hnew;
                        g_agg[v * H + lane] = 0.0f;
                        float pv = hnew * aw0;
                        float qv = hnew * aw1;
                        #pragma unroll
                        for (int off = 16; off; off >>= 1) {
                            pv += __shfl_down_sync(0xffffffffu, pv, off);
                            qv += __shfl_down_sync(0xffffffffu, qv, off);
                        }
                        if (lane == 0) { g_p[v] = pv; g_q[v] = qv; g_nsum[v] = 0.0f; }
                    }
                }
            }
        }
        if (step < NUM_STEPS - 1) grid_barrier(&bsense);       // B-gru (x2)
    }
}

// ---------------- launch ----------------------------------------------------
extern "C" void kernel_launch(void* const* d_in, const int* in_sizes, int n_in,
                              void* d_out, int out_size) {
    k_fused<<<G, TPB>>>(
        (const int*)d_in[0], (const int*)d_in[1], (const int*)d_in[2],
        (const int*)d_in[3], (const float*)d_in[4], (const float*)d_in[5],
        (const float*)d_in[6], (const float*)d_in[7], (const float*)d_in[8],
        (const float*)d_in[9], (const float*)d_in[10], (const float*)d_in[11],
        (const float*)d_in[12], (const float*)d_in[13], (const float*)d_in[14],
        (const float*)d_in[15], (const float*)d_in[16], (const float*)d_in[17],
        (const float*)d_in[18], (const float*)d_in[19], (const float*)d_in[20],
        (float*)d_out);
}